// round 8
// baseline (speedup 1.0000x reference)
#include <cuda_runtime.h>

// Problem constants (fixed by the dataset)
#define HG   256
#define WG   256
#define BB   2
#define CC   4
#define NN   1024
#define TILE 16                 // 16x16 grid cells per CTA
#define TPB  512                // TWO threads per cell
#define TILES_X (WG / TILE)     // 16
#define TILES_Y (HG / TILE)     // 16
#define PPT  (NN / TPB)         // 2 points per thread
#define CAP  512                // survivor capacity (expected ~35)
#define NW   (TPB / 32)         // 16 warps

// half-diagonal of a 16x16-cell tile: (TILE/2)/256 * sqrt(2)
#define RT 0.0441941738f

__global__ __launch_bounds__(TPB)
void nn_tile_kernel(const float* __restrict__ R_pc,   // [B, C, N]
                    const float* __restrict__ XY_pc,  // [B, 2, N]
                    float* __restrict__ out)          // [B, C, H, W]
{
    __shared__ float4 sv[CAP];       // survivors (px, py, pn2, idx), n-ORDERED
    __shared__ float  s_warpmin[NW];
    __shared__ int    s_wcnt[NW];
    __shared__ float  s_pbest[TILE * TILE];
    __shared__ int    s_pbestn[TILE * TILE];

    const int tile = blockIdx.x;           // 0..255
    const int b    = blockIdx.y;           // 0..1
    const int tj   = tile % TILES_X;
    const int ti   = tile / TILES_X;
    const int t    = threadIdx.x;
    const int wid  = t >> 5;
    const int lane = t & 31;

    const float inv = 1.0f / 256.0f;
    const float cx  = (float)(tj * TILE + TILE / 2) * inv;  // tile center
    const float cy  = (float)(ti * TILE + TILE / 2) * inv;

    const float* Xb = XY_pc + b * 2 * NN;

    // ---- Load 2 consecutive points per thread (coalesced LDG.64) ----
    const int nbase = t * PPT;             // thread t owns n = 2t, 2t+1
    float2 pxv = *(const float2*)(Xb + nbase);
    float2 pyv = *(const float2*)(Xb + NN + nbase);
    float px[PPT] = {pxv.x, pxv.y};
    float py[PPT] = {pyv.x, pyv.y};

    // ---- Phase 1: block-min distance^2 from tile center ----
    float d2c[PPT];
    #pragma unroll
    for (int k = 0; k < PPT; k++) {
        float dx = px[k] - cx, dy = py[k] - cy;
        d2c[k] = fmaf(dx, dx, dy * dy);
    }
    float dmin = fminf(d2c[0], d2c[1]);
    #pragma unroll
    for (int o = 16; o > 0; o >>= 1)
        dmin = fminf(dmin, __shfl_xor_sync(0xffffffffu, dmin, o));
    if (lane == 0) s_warpmin[wid] = dmin;
    __syncthreads();

    float rmin = 3.4e38f;
    {
        const float4* wm4 = (const float4*)s_warpmin;
        #pragma unroll
        for (int i = 0; i < NW / 4; i++) {
            float4 v = wm4[i];
            rmin = fminf(rmin, fminf(fminf(v.x, v.y), fminf(v.z, v.w)));
        }
    }
    // cull radius: r_min + 2*r_tile (+ fp safety margin). Exact bound:
    // a point farther from the center cannot be nearest for any cell here.
    float Rrad = sqrtf(rmin) + 2.0f * RT + 1e-3f;
    float R2   = Rrad * Rrad;

    // ---- Phase 2: ORDERED compaction (survivor list ascending in n) ----
    bool s0 = (d2c[0] <= R2);
    bool s1 = (d2c[1] <= R2);
    int  cnt = (int)s0 + (int)s1;
    unsigned bal1 = __ballot_sync(0xffffffffu, cnt >= 1);
    unsigned bal2 = __ballot_sync(0xffffffffu, cnt >= 2);
    unsigned ltm  = (1u << lane) - 1u;
    int lanepre   = __popc(bal1 & ltm) + __popc(bal2 & ltm);
    if (lane == 0) s_wcnt[wid] = __popc(bal1) + __popc(bal2);
    __syncthreads();

    int woff = 0, M = 0;
    #pragma unroll
    for (int w = 0; w < NW; w++) {
        int c = s_wcnt[w];
        woff += (w < wid) ? c : 0;
        M += c;
    }
    if (M <= CAP) {
        int pos = woff + lanepre;
        if (s0) {
            float pn2 = __fadd_rn(__fmul_rn(px[0], px[0]),
                                  __fmul_rn(py[0], py[0]));
            sv[pos++] = make_float4(px[0], py[0], pn2, __int_as_float(nbase));
        }
        if (s1) {
            float pn2 = __fadd_rn(__fmul_rn(px[1], px[1]),
                                  __fmul_rn(py[1], py[1]));
            sv[pos] = make_float4(px[1], py[1], pn2, __int_as_float(nbase + 1));
        }
    }
    __syncthreads();

    // ---- Phase 3: per-cell argmin; each cell split across 2 threads ----
    const int cell = t & (TILE * TILE - 1);
    const int half = t >> 8;               // 0 = low-n segment owner
    const int jl = cell & (TILE - 1);
    const int il = cell >> 4;
    const int gi = ti * TILE + il;
    const int gj = tj * TILE + jl;
    const float gx = ((float)gj + 0.5f) * inv;
    const float gy = ((float)gi + 0.5f) * inv;

    float best  = 3.4e38f;
    int   bestN = 0;

    if (M <= CAP) {
        // list is n-ascending, so strict < keeps the FIRST index at the min
        // (jnp.argmin rule). half 0 scans the lower-n segment.
        int mh = M >> 1;
        int lo = half ? mh : 0;
        int hi = half ? M : mh;
        for (int m = lo; m < hi; m++) {
            float4 p  = sv[m];
            // mirror reference: d2 = pn2 - 2*fma(gy,py, gx*px)
            float dot = fmaf(gy, p.y, __fmul_rn(gx, p.x));
            float d2  = __fadd_rn(p.z, -2.0f * dot);
            if (d2 < best) {
                best  = d2;
                bestN = __float_as_int(p.w);
            }
        }
    } else if (half == 0) {
        // overflow fallback (never expected): full scan, n ascending
        for (int n = 0; n < NN; n++) {
            float qx = Xb[n], qy = Xb[NN + n];
            float pn2 = __fadd_rn(__fmul_rn(qx, qx), __fmul_rn(qy, qy));
            float dot = fmaf(gy, qy, __fmul_rn(gx, qx));
            float d2  = __fadd_rn(pn2, -2.0f * dot);
            if (d2 < best) { best = d2; bestN = n; }
        }
    }

    // ---- Merge partner halves (strict <: tie -> low-n half wins) ----
    if (half == 1) {
        s_pbest[cell]  = best;
        s_pbestn[cell] = bestN;
    }
    __syncthreads();

    if (half == 0) {
        float bB = s_pbest[cell];
        int   nB = s_pbestn[cell];
        if (bB < best) { best = bB; bestN = nB; }

        // ---- Gather channel values and write output ----
        const float* Rb = R_pc + b * CC * NN;
        float* ob = out + ((size_t)b * CC * HG * WG) + (size_t)gi * WG + gj;
        #pragma unroll
        for (int c = 0; c < CC; c++)
            ob[(size_t)c * HG * WG] = Rb[c * NN + bestN];
    }
}

extern "C" void kernel_launch(void* const* d_in, const int* in_sizes, int n_in,
                              void* d_out, int out_size)
{
    (void)in_sizes; (void)n_in; (void)out_size;
    const float* R_pc  = (const float*)d_in[0];  // [2,4,1024]
    const float* XY_pc = (const float*)d_in[1];  // [2,2,1024]
    float* out = (float*)d_out;                  // [2,4,256,256]

    dim3 grid(TILES_X * TILES_Y, BB);
    nn_tile_kernel<<<grid, TPB>>>(R_pc, XY_pc, out);
}

// round 11
// speedup vs baseline: 2.1871x; 2.1871x over previous
#include <cuda_runtime.h>

// Problem constants (fixed by the dataset)
#define HG   256
#define WG   256
#define BB   2
#define CC   4
#define NN   1024
#define TILE 16                // 16x16 grid cells per CTA
#define TPB  256               // one thread per cell
#define TILES_X (WG / TILE)    // 16
#define TILES_Y (HG / TILE)    // 16
#define PPT  (NN / TPB)        // 4 points per thread
#define CAP  512               // survivor capacity (expected ~35)
#define NW   (TPB / 32)        // 8 warps

// half-diagonal of a 16x16-cell tile: (TILE/2)/256 * sqrt(2)
#define RT 0.0441941738f

__global__ __launch_bounds__(TPB)
void nn_tile_kernel(const float* __restrict__ R_pc,   // [B, C, N]
                    const float* __restrict__ XY_pc,  // [B, 2, N]
                    float* __restrict__ out)          // [B, C, H, W]
{
    __shared__ float4 sv[CAP + 1];   // survivors (px,py,pn2,idx), n-ASCENDING
    __shared__ float  s_warpmin[NW];
    __shared__ int    s_wcnt[NW];

    const int tile = blockIdx.x;           // 0..255
    const int b    = blockIdx.y;           // 0..1
    const int tj   = tile % TILES_X;
    const int ti   = tile / TILES_X;
    const int t    = threadIdx.x;
    const int wid  = t >> 5;
    const int lane = t & 31;

    const float inv = 1.0f / 256.0f;
    const float cx  = (float)(tj * TILE + TILE / 2) * inv;  // tile center
    const float cy  = (float)(ti * TILE + TILE / 2) * inv;

    const float* Xb = XY_pc + b * 2 * NN;

    // ---- Load 4 consecutive points per thread ONCE (two LDG.128) ----
    const int nbase = t * PPT;             // thread t owns n = 4t..4t+3
    float4 px4 = *(const float4*)(Xb + nbase);
    float4 py4 = *(const float4*)(Xb + NN + nbase);
    float px[PPT] = {px4.x, px4.y, px4.z, px4.w};
    float py[PPT] = {py4.x, py4.y, py4.z, py4.w};

    // ---- Phase 1: block-min distance^2 from tile center ----
    float d2c[PPT];
    float dmin = 3.4e38f;
    #pragma unroll
    for (int k = 0; k < PPT; k++) {
        float dx = px[k] - cx, dy = py[k] - cy;
        d2c[k] = fmaf(dx, dx, dy * dy);
        dmin = fminf(dmin, d2c[k]);
    }
    #pragma unroll
    for (int o = 16; o > 0; o >>= 1)
        dmin = fminf(dmin, __shfl_xor_sync(0xffffffffu, dmin, o));
    if (lane == 0) s_warpmin[wid] = dmin;
    __syncthreads();

    float rmin;
    {
        const float4* wm4 = (const float4*)s_warpmin;
        float4 v0 = wm4[0], v1 = wm4[1];
        rmin = fminf(fminf(fminf(v0.x, v0.y), fminf(v0.z, v0.w)),
                     fminf(fminf(v1.x, v1.y), fminf(v1.z, v1.w)));
    }
    // cull radius: r_min + 2*r_tile (+ fp safety margin). Exact bound:
    // a point farther from the center cannot be nearest for any cell here.
    float Rrad = sqrtf(rmin) + 2.0f * RT + 1e-3f;
    float R2   = Rrad * Rrad;

    // ---- Phase 2: ORDERED ballot compaction (list ascending in n) ----
    bool s0 = (d2c[0] <= R2), s1 = (d2c[1] <= R2);
    bool s2 = (d2c[2] <= R2), s3 = (d2c[3] <= R2);
    int  cnt = (int)s0 + (int)s1 + (int)s2 + (int)s3;
    unsigned b1 = __ballot_sync(0xffffffffu, cnt >= 1);
    unsigned b2 = __ballot_sync(0xffffffffu, cnt >= 2);
    unsigned b3 = __ballot_sync(0xffffffffu, cnt >= 3);
    unsigned b4 = __ballot_sync(0xffffffffu, cnt >= 4);
    unsigned ltm = (1u << lane) - 1u;
    int lanepre = __popc(b1 & ltm) + __popc(b2 & ltm)
                + __popc(b3 & ltm) + __popc(b4 & ltm);
    if (lane == 0)
        s_wcnt[wid] = __popc(b1) + __popc(b2) + __popc(b3) + __popc(b4);
    __syncthreads();

    int woff = 0, M = 0;
    #pragma unroll
    for (int w = 0; w < NW; w++) {
        int c = s_wcnt[w];
        woff += (w < wid) ? c : 0;
        M += c;
    }
    if (M <= CAP) {
        int pos = woff + lanepre;
        #pragma unroll
        for (int k = 0; k < PPT; k++) {
            bool s = (k == 0) ? s0 : (k == 1) ? s1 : (k == 2) ? s2 : s3;
            if (s) {
                // pn2 matches reference: round(px*px) + round(py*py)
                float pn2 = __fadd_rn(__fmul_rn(px[k], px[k]),
                                      __fmul_rn(py[k], py[k]));
                sv[pos++] = make_float4(px[k], py[k], pn2,
                                        __int_as_float(nbase + k));
            }
        }
    }
    __syncthreads();

    // ---- Phase 3: per-cell argmin over n-ascending survivors ----
    const int jl = t & (TILE - 1);
    const int il = t >> 4;
    const int gi = ti * TILE + il;
    const int gj = tj * TILE + jl;
    const float gx = ((float)gj + 0.5f) * inv;
    const float gy = ((float)gi + 0.5f) * inv;

    float best  = 3.4e38f;
    int   bestN = 0;

    if (M <= CAP) {
        // list ascending in n -> strict < keeps FIRST index at the min
        // (jnp.argmin rule). Prefetch next entry to hide LDS latency.
        float4 nxt = sv[0];
        for (int m = 0; m < M; m++) {
            float4 p = nxt;
            nxt = sv[m + 1];               // in-bounds: m+1 <= M <= CAP
            // mirror reference: d2 = pn2 - 2*fma(gy,py, gx*px)
            float dot = fmaf(gy, p.y, __fmul_rn(gx, p.x));
            float d2  = __fadd_rn(p.z, -2.0f * dot);
            if (d2 < best) {
                best  = d2;
                bestN = __float_as_int(p.w);
            }
        }
    } else {
        // overflow fallback (never expected): full scan, n ascending
        for (int n = 0; n < NN; n++) {
            float qx = Xb[n], qy = Xb[NN + n];
            float pn2 = __fadd_rn(__fmul_rn(qx, qx), __fmul_rn(qy, qy));
            float dot = fmaf(gy, qy, __fmul_rn(gx, qx));
            float d2  = __fadd_rn(pn2, -2.0f * dot);
            if (d2 < best) { best = d2; bestN = n; }
        }
    }

    // ---- Gather channel values and write output ----
    const float* Rb = R_pc + b * CC * NN;
    float* ob = out + ((size_t)b * CC * HG * WG) + (size_t)gi * WG + gj;
    #pragma unroll
    for (int c = 0; c < CC; c++)
        ob[(size_t)c * HG * WG] = Rb[c * NN + bestN];
}

extern "C" void kernel_launch(void* const* d_in, const int* in_sizes, int n_in,
                              void* d_out, int out_size)
{
    (void)in_sizes; (void)n_in; (void)out_size;
    const float* R_pc  = (const float*)d_in[0];  // [2,4,1024]
    const float* XY_pc = (const float*)d_in[1];  // [2,2,1024]
    float* out = (float*)d_out;                  // [2,4,256,256]

    dim3 grid(TILES_X * TILES_Y, BB);
    nn_tile_kernel<<<grid, TPB>>>(R_pc, XY_pc, out);
}